// round 3
// baseline (speedup 1.0000x reference)
#include <cuda_runtime.h>
#include <math.h>

#define WPB 8
#define NTHREADS (WPB * 32)

// blade masks M = {0,1,2,4,3,5,6,7}; IDX is self-inverse.
// J[i][k] = blade index of mask(i) ^ mask(k)  (output blade of h_i * xr_k)
__constant__ int c_J[64] = {
 0,1,2,3,4,5,6,7,
 1,0,4,5,2,3,7,6,
 2,4,0,6,1,7,3,5,
 3,5,6,0,7,1,2,4,
 4,2,1,7,0,6,5,3,
 5,3,7,1,6,0,4,2,
 6,7,3,2,5,4,0,1,
 7,6,5,4,3,2,1,0};
__constant__ int c_G[8] = {0,1,1,1,2,2,2,3};

extern __shared__ float smem[];
// smem layout (floats):
//   w1s : [    0,  2048)   w1[(m*4+g)*32+c]
//   wls : [ 2048,  6144)   wl[(m*4+g)*32+c]
//   wrs : [ 6144, 10240)   wr[(m*4+g)*32+c]
//   fgp : [10240, 12288)   sign*gp_w  [(i*8+k)*32+c]
//   per-warp staging: 384 floats each (xs 128 + hs 256), base 12288
// total = 15360 floats = 61440 bytes

__global__ __launch_bounds__(NTHREADS)
void cge_kernel(const float* __restrict__ x,
                const float* __restrict__ w1,
                const float* __restrict__ b1,
                const float* __restrict__ a_relu,
                const float* __restrict__ b_relu,
                const float* __restrict__ wl,
                const float* __restrict__ bl,
                const float* __restrict__ wr,
                const float* __restrict__ a_norm,
                const float* __restrict__ gp_w,
                const float* __restrict__ a_ln,
                const float* __restrict__ cayley,
                float* __restrict__ out,
                int B, int nwarps)
{
    float* w1s = smem;
    float* wls = smem + 2048;
    float* wrs = smem + 6144;
    float* fgp = smem + 10240;
    const int tid  = threadIdx.x;
    const int warp = tid >> 5;
    const int c    = tid & 31;
    float* xs = smem + 12288 + warp * 384;
    float* hs = xs + 128;

    // ---- stage weights into SMEM (once per block) ----
    for (int d = tid; d < 2048; d += NTHREADS) {
        int m = d >> 7, g = (d >> 5) & 3, cc = d & 31;
        w1s[d] = w1[cc * 64 + m * 4 + g];
    }
    for (int d = tid; d < 4096; d += NTHREADS) {
        int m = d >> 7, g = (d >> 5) & 3, cc = d & 31;
        wls[d] = wl[cc * 128 + m * 4 + g];
        wrs[d] = wr[cc * 128 + m * 4 + g];
    }
    for (int d = tid; d < 2048; d += NTHREADS) {
        int p = d >> 5, cc = d & 31;
        int i = p >> 3, k = p & 7;
        int j = c_J[p];
        float s = cayley[(i * 8 + j) * 8 + k];           // +-1 from the input table
        fgp[d] = s * gp_w[cc * 64 + c_G[i] * 16 + c_G[j] * 4 + c_G[k]];
    }
    __syncthreads();

    // ---- per-channel constants in registers ----
    const float ar0 = a_relu[c*4+0], ar1 = a_relu[c*4+1], ar2 = a_relu[c*4+2], ar3 = a_relu[c*4+3];
    const float br0 = b_relu[c*4+0], br1 = b_relu[c*4+1], br2 = b_relu[c*4+2], br3 = b_relu[c*4+3];
    const float b1c = b1[c], blc = bl[c], alnc = a_ln[c];
    const float sg0 = 1.f / (1.f + expf(-a_norm[c*4+0]));
    const float sg1 = 1.f / (1.f + expf(-a_norm[c*4+1]));
    const float sg2 = 1.f / (1.f + expf(-a_norm[c*4+2]));
    const float sg3 = 1.f / (1.f + expf(-a_norm[c*4+3]));

    static constexpr int Jt[8][8] = {
        {0,1,2,3,4,5,6,7},
        {1,0,4,5,2,3,7,6},
        {2,4,0,6,1,7,3,5},
        {3,5,6,0,7,1,2,4},
        {4,2,1,7,0,6,5,3},
        {5,3,7,1,6,0,4,2},
        {6,7,3,2,5,4,0,1},
        {7,6,5,4,3,2,1,0}};

    for (int b = blockIdx.x * WPB + warp; b < B; b += nwarps) {
        // load x[b] (128 floats): one float4 per lane, stage to SMEM
        const float4 xv = ((const float4*)(x + (long)b * 128))[c];
        ((float4*)xs)[c] = xv;
        __syncwarp();

        // ---- MVLinear 16->32 (lane c = out channel c) ----
        float h[8] = {0.f,0.f,0.f,0.f,0.f,0.f,0.f,0.f};
        #pragma unroll
        for (int m = 0; m < 16; m++) {
            const float4 xa = *(const float4*)(xs + m * 8);
            const float4 xb = *(const float4*)(xs + m * 8 + 4);
            const float u0 = w1s[(m*4+0)*32 + c];
            const float u1 = w1s[(m*4+1)*32 + c];
            const float u2 = w1s[(m*4+2)*32 + c];
            const float u3 = w1s[(m*4+3)*32 + c];
            h[0] = fmaf(xa.x, u0, h[0]); h[1] = fmaf(xa.y, u1, h[1]);
            h[2] = fmaf(xa.z, u1, h[2]); h[3] = fmaf(xa.w, u1, h[3]);
            h[4] = fmaf(xb.x, u2, h[4]); h[5] = fmaf(xb.y, u2, h[5]);
            h[6] = fmaf(xb.z, u2, h[6]); h[7] = fmaf(xb.w, u3, h[7]);
        }
        h[0] += b1c;

        // ---- MVReLU ----
        const float q1 = h[1]*h[1] + h[2]*h[2] + h[3]*h[3];
        const float q2 = h[4]*h[4] + h[5]*h[5] + h[6]*h[6];
        const float q3 = h[7]*h[7];
        const float g0 = fmaxf(fmaf(ar0, h[0], br0), 0.f);
        const float g1 = fmaxf(fmaf(ar1, q1,  br1), 0.f);
        const float g2 = fmaxf(fmaf(ar2, q2,  br2), 0.f);
        const float g3 = fmaxf(fmaf(ar3, q3,  br3), 0.f);
        h[0] *= g0; h[1] *= g1; h[2] *= g1; h[3] *= g1;
        h[4] *= g2; h[5] *= g2; h[6] *= g2; h[7] *= g3;

        // stage gated h for cross-channel matmuls
        __syncwarp();
        *(float4*)(hs + c * 8)     = make_float4(h[0], h[1], h[2], h[3]);
        *(float4*)(hs + c * 8 + 4) = make_float4(h[4], h[5], h[6], h[7]);
        __syncwarp();

        // ---- xl = wl*h  and  xr = wr*h  (32x32 per-grade matmuls) ----
        float xl[8] = {0.f,0.f,0.f,0.f,0.f,0.f,0.f,0.f};
        float xr[8] = {0.f,0.f,0.f,0.f,0.f,0.f,0.f,0.f};
        #pragma unroll
        for (int m = 0; m < 32; m++) {
            const float4 ha = *(const float4*)(hs + m * 8);
            const float4 hb = *(const float4*)(hs + m * 8 + 4);
            const float l0 = wls[(m*4+0)*32 + c];
            const float l1 = wls[(m*4+1)*32 + c];
            const float l2 = wls[(m*4+2)*32 + c];
            const float l3 = wls[(m*4+3)*32 + c];
            const float r0 = wrs[(m*4+0)*32 + c];
            const float r1 = wrs[(m*4+1)*32 + c];
            const float r2 = wrs[(m*4+2)*32 + c];
            const float r3 = wrs[(m*4+3)*32 + c];
            xl[0] = fmaf(ha.x, l0, xl[0]);  xr[0] = fmaf(ha.x, r0, xr[0]);
            xl[1] = fmaf(ha.y, l1, xl[1]);  xr[1] = fmaf(ha.y, r1, xr[1]);
            xl[2] = fmaf(ha.z, l1, xl[2]);  xr[2] = fmaf(ha.z, r1, xr[2]);
            xl[3] = fmaf(ha.w, l1, xl[3]);  xr[3] = fmaf(ha.w, r1, xr[3]);
            xl[4] = fmaf(hb.x, l2, xl[4]);  xr[4] = fmaf(hb.x, r2, xr[4]);
            xl[5] = fmaf(hb.y, l2, xl[5]);  xr[5] = fmaf(hb.y, r2, xr[5]);
            xl[6] = fmaf(hb.z, l2, xl[6]);  xr[6] = fmaf(hb.z, r2, xr[6]);
            xl[7] = fmaf(hb.w, l3, xl[7]);  xr[7] = fmaf(hb.w, r3, xr[7]);
        }

        // ---- normalize xr (grade-wise, learned interpolation toward unit norm) ----
        const float p0 = xr[0]*xr[0];
        const float p1 = xr[1]*xr[1] + xr[2]*xr[2] + xr[3]*xr[3];
        const float p2 = xr[4]*xr[4] + xr[5]*xr[5] + xr[6]*xr[6];
        const float p3 = xr[7]*xr[7];
        const float n0 = fmaf(sg0, sqrtf(p0) - 1.f, 1.f);
        const float n1 = fmaf(sg1, sqrtf(p1) - 1.f, 1.f);
        const float n2 = fmaf(sg2, sqrtf(p2) - 1.f, 1.f);
        const float n3 = fmaf(sg3, sqrtf(p3) - 1.f, 1.f);
        const float i0 = 1.f / (n0 + 1e-6f);
        const float i1 = 1.f / (n1 + 1e-6f);
        const float i2 = 1.f / (n2 + 1e-6f);
        const float i3 = 1.f / (n3 + 1e-6f);
        xr[0] *= i0; xr[1] *= i1; xr[2] *= i1; xr[3] *= i1;
        xr[4] *= i2; xr[5] *= i2; xr[6] *= i2; xr[7] *= i3;

        // ---- geometric product: acc_j += sign*gpw * h_i * xr_k, j = blade(i^k) ----
        xl[0] += blc;
        #pragma unroll
        for (int i = 0; i < 8; i++) {
            const float hi = h[i];
            #pragma unroll
            for (int k = 0; k < 8; k++) {
                const int j = Jt[i][k];
                xl[j] = fmaf(fgp[(i * 8 + k) * 32 + c], hi * xr[k], xl[j]);
            }
        }

        // ---- scale 1/sqrt(2), MVLayerNorm (mean channel norm) ----
        const float is2 = 0.70710678118654752f;
        float s = 0.f;
        #pragma unroll
        for (int i = 0; i < 8; i++) { xl[i] *= is2; s = fmaf(xl[i], xl[i], s); }
        float nc = sqrtf(s);
        #pragma unroll
        for (int off = 16; off; off >>= 1)
            nc += __shfl_xor_sync(0xffffffffu, nc, off);
        const float sc = alnc / (nc * (1.f / 32.f) + 1e-6f);

        float4* op = (float4*)(out + (long)b * 256);
        op[c * 2]     = make_float4(xl[0]*sc, xl[1]*sc, xl[2]*sc, xl[3]*sc);
        op[c * 2 + 1] = make_float4(xl[4]*sc, xl[5]*sc, xl[6]*sc, xl[7]*sc);
    }
}

extern "C" void kernel_launch(void* const* d_in, const int* in_sizes, int n_in,
                              void* d_out, int out_size) {
    const float* x      = (const float*)d_in[0];
    const float* w1     = (const float*)d_in[1];
    const float* b1     = (const float*)d_in[2];
    const float* a_relu = (const float*)d_in[3];
    const float* b_relu = (const float*)d_in[4];
    const float* wl     = (const float*)d_in[5];
    const float* bl     = (const float*)d_in[6];
    const float* wr     = (const float*)d_in[7];
    const float* a_norm = (const float*)d_in[8];
    const float* gp_w   = (const float*)d_in[9];
    const float* a_ln   = (const float*)d_in[10];
    const float* cayley = (const float*)d_in[11];
    float* out = (float*)d_out;

    const int B = in_sizes[0] / 128;  // [B, 16, 8]
    const int blocks = 296;           // 2 blocks/SM on 148 SMs, grid-stride
    const int nwarps = blocks * WPB;
    const size_t shmem = 15360 * sizeof(float);  // 60 KB dynamic

    cudaFuncSetAttribute(cge_kernel, cudaFuncAttributeMaxDynamicSharedMemorySize,
                         (int)shmem);
    cge_kernel<<<blocks, NTHREADS, shmem>>>(x, w1, b1, a_relu, b_relu, wl, bl, wr,
                                            a_norm, gp_w, a_ln, cayley, out,
                                            B, nwarps);
}

// round 5
// speedup vs baseline: 1.0218x; 1.0218x over previous
#include <cuda_runtime.h>
#include <math.h>

#define WPB 8
#define NTHREADS (WPB * 32)
#define EPW 4   // elements per warp per iteration

__constant__ int c_J[64] = {
 0,1,2,3,4,5,6,7,
 1,0,4,5,2,3,7,6,
 2,4,0,6,1,7,3,5,
 3,5,6,0,7,1,2,4,
 4,2,1,7,0,6,5,3,
 5,3,7,1,6,0,4,2,
 6,7,3,2,5,4,0,1,
 7,6,5,4,3,2,1,0};
__constant__ int c_G[8] = {0,1,1,1,2,2,2,3};

extern __shared__ float smem[];
// smem layout (floats):
//   w1v : [    0,  2048)   [m=16][c=32][g=4]  (vector loads)
//   wlv : [ 2048,  6144)   [m=32][c=32][g=4]
//   wrv : [ 6144, 10240)   [m=32][c=32][g=4]
//   fgp : [10240, 12288)   sign*gp_w [(i*8+k)*32+c]
//   per-warp staging: 1536 floats each: xs[4][128], hs[4][256], base 12288
// total = 12288 + 8*1536 = 24576 floats = 98304 bytes

__global__ __launch_bounds__(NTHREADS, 2)
void cge_kernel(const float* __restrict__ x,
                const float* __restrict__ w1,
                const float* __restrict__ b1,
                const float* __restrict__ a_relu,
                const float* __restrict__ b_relu,
                const float* __restrict__ wl,
                const float* __restrict__ bl,
                const float* __restrict__ wr,
                const float* __restrict__ a_norm,
                const float* __restrict__ gp_w,
                const float* __restrict__ a_ln,
                const float* __restrict__ cayley,
                float* __restrict__ out,
                int ngroups, int nwarps)
{
    float* w1v = smem;
    float* wlv = smem + 2048;
    float* wrv = smem + 6144;
    float* fgp = smem + 10240;
    const int tid  = threadIdx.x;
    const int warp = tid >> 5;
    const int c    = tid & 31;
    float* xs = smem + 12288 + warp * 1536;   // [e][128]
    float* hs = xs + EPW * 128;               // [e][256]

    // ---- stage weights into SMEM (vector-load-friendly layouts) ----
    for (int d = tid; d < 2048; d += NTHREADS) {
        int m = d >> 7, cc = (d >> 2) & 31, g = d & 3;
        w1v[d] = w1[cc * 64 + m * 4 + g];
    }
    for (int d = tid; d < 4096; d += NTHREADS) {
        int m = d >> 7, cc = (d >> 2) & 31, g = d & 3;
        wlv[d] = wl[cc * 128 + m * 4 + g];
        wrv[d] = wr[cc * 128 + m * 4 + g];
    }
    for (int d = tid; d < 2048; d += NTHREADS) {
        int p = d >> 5, cc = d & 31;
        int i = p >> 3, k = p & 7;
        int j = c_J[p];
        float s = cayley[(i * 8 + j) * 8 + k];
        fgp[d] = s * gp_w[cc * 64 + c_G[i] * 16 + c_G[j] * 4 + c_G[k]];
    }
    __syncthreads();

    // ---- per-channel constants ----
    const float ar0 = a_relu[c*4+0], ar1 = a_relu[c*4+1], ar2 = a_relu[c*4+2], ar3 = a_relu[c*4+3];
    const float br0 = b_relu[c*4+0], br1 = b_relu[c*4+1], br2 = b_relu[c*4+2], br3 = b_relu[c*4+3];
    const float b1c = b1[c], blc = bl[c], alnc = a_ln[c];
    const float sg0 = 1.f / (1.f + expf(-a_norm[c*4+0]));
    const float sg1 = 1.f / (1.f + expf(-a_norm[c*4+1]));
    const float sg2 = 1.f / (1.f + expf(-a_norm[c*4+2]));
    const float sg3 = 1.f / (1.f + expf(-a_norm[c*4+3]));

    static constexpr int Jt[8][8] = {
        {0,1,2,3,4,5,6,7},
        {1,0,4,5,2,3,7,6},
        {2,4,0,6,1,7,3,5},
        {3,5,6,0,7,1,2,4},
        {4,2,1,7,0,6,5,3},
        {5,3,7,1,6,0,4,2},
        {6,7,3,2,5,4,0,1},
        {7,6,5,4,3,2,1,0}};

    for (int g = blockIdx.x * WPB + warp; g < ngroups; g += nwarps) {
        const long b0 = (long)g * EPW;

        // ---- stage x for 4 elements ----
        #pragma unroll
        for (int e = 0; e < EPW; e++) {
            const float4 xv = ((const float4*)(x + (b0 + e) * 128))[c];
            ((float4*)(xs + e * 128))[c] = xv;
        }
        __syncwarp();

        // ---- MVLinear 16->32 ----
        float h[EPW][8];
        #pragma unroll
        for (int e = 0; e < EPW; e++)
            #pragma unroll
            for (int i = 0; i < 8; i++) h[e][i] = 0.f;

        #pragma unroll
        for (int m = 0; m < 16; m++) {
            const float4 u = ((const float4*)w1v)[m * 32 + c];
            #pragma unroll
            for (int e = 0; e < EPW; e++) {
                const float4 xa = *(const float4*)(xs + e * 128 + m * 8);
                const float4 xb = *(const float4*)(xs + e * 128 + m * 8 + 4);
                h[e][0] = fmaf(xa.x, u.x, h[e][0]); h[e][1] = fmaf(xa.y, u.y, h[e][1]);
                h[e][2] = fmaf(xa.z, u.y, h[e][2]); h[e][3] = fmaf(xa.w, u.y, h[e][3]);
                h[e][4] = fmaf(xb.x, u.z, h[e][4]); h[e][5] = fmaf(xb.y, u.z, h[e][5]);
                h[e][6] = fmaf(xb.z, u.z, h[e][6]); h[e][7] = fmaf(xb.w, u.w, h[e][7]);
            }
        }

        // ---- MVReLU + stage gated h ----
        __syncwarp();
        #pragma unroll
        for (int e = 0; e < EPW; e++) {
            h[e][0] += b1c;
            const float q1 = h[e][1]*h[e][1] + h[e][2]*h[e][2] + h[e][3]*h[e][3];
            const float q2 = h[e][4]*h[e][4] + h[e][5]*h[e][5] + h[e][6]*h[e][6];
            const float q3 = h[e][7]*h[e][7];
            const float g0 = fmaxf(fmaf(ar0, h[e][0], br0), 0.f);
            const float g1 = fmaxf(fmaf(ar1, q1,  br1), 0.f);
            const float g2 = fmaxf(fmaf(ar2, q2,  br2), 0.f);
            const float g3 = fmaxf(fmaf(ar3, q3,  br3), 0.f);
            h[e][0] *= g0; h[e][1] *= g1; h[e][2] *= g1; h[e][3] *= g1;
            h[e][4] *= g2; h[e][5] *= g2; h[e][6] *= g2; h[e][7] *= g3;
            *(float4*)(hs + e * 256 + c * 8)     = make_float4(h[e][0], h[e][1], h[e][2], h[e][3]);
            *(float4*)(hs + e * 256 + c * 8 + 4) = make_float4(h[e][4], h[e][5], h[e][6], h[e][7]);
        }
        __syncwarp();

        // ---- xl = wl*h and xr = wr*h (32x32 per-grade matmuls) ----
        float xl[EPW][8], xr[EPW][8];
        #pragma unroll
        for (int e = 0; e < EPW; e++)
            #pragma unroll
            for (int i = 0; i < 8; i++) { xl[e][i] = 0.f; xr[e][i] = 0.f; }

        #pragma unroll
        for (int m = 0; m < 32; m++) {
            const float4 lw = ((const float4*)wlv)[m * 32 + c];
            const float4 rw = ((const float4*)wrv)[m * 32 + c];
            #pragma unroll
            for (int e = 0; e < EPW; e++) {
                const float4 ha = *(const float4*)(hs + e * 256 + m * 8);
                const float4 hb = *(const float4*)(hs + e * 256 + m * 8 + 4);
                xl[e][0] = fmaf(ha.x, lw.x, xl[e][0]);  xr[e][0] = fmaf(ha.x, rw.x, xr[e][0]);
                xl[e][1] = fmaf(ha.y, lw.y, xl[e][1]);  xr[e][1] = fmaf(ha.y, rw.y, xr[e][1]);
                xl[e][2] = fmaf(ha.z, lw.y, xl[e][2]);  xr[e][2] = fmaf(ha.z, rw.y, xr[e][2]);
                xl[e][3] = fmaf(ha.w, lw.y, xl[e][3]);  xr[e][3] = fmaf(ha.w, rw.y, xr[e][3]);
                xl[e][4] = fmaf(hb.x, lw.z, xl[e][4]);  xr[e][4] = fmaf(hb.x, rw.z, xr[e][4]);
                xl[e][5] = fmaf(hb.y, lw.z, xl[e][5]);  xr[e][5] = fmaf(hb.y, rw.z, xr[e][5]);
                xl[e][6] = fmaf(hb.z, lw.z, xl[e][6]);  xr[e][6] = fmaf(hb.z, rw.z, xr[e][6]);
                xl[e][7] = fmaf(hb.w, lw.w, xl[e][7]);  xr[e][7] = fmaf(hb.w, rw.w, xr[e][7]);
            }
        }

        // ---- normalize xr ----
        #pragma unroll
        for (int e = 0; e < EPW; e++) {
            const float p0 = xr[e][0]*xr[e][0];
            const float p1 = xr[e][1]*xr[e][1] + xr[e][2]*xr[e][2] + xr[e][3]*xr[e][3];
            const float p2 = xr[e][4]*xr[e][4] + xr[e][5]*xr[e][5] + xr[e][6]*xr[e][6];
            const float p3 = xr[e][7]*xr[e][7];
            const float n0 = fmaf(sg0, sqrtf(p0) - 1.f, 1.f);
            const float n1 = fmaf(sg1, sqrtf(p1) - 1.f, 1.f);
            const float n2 = fmaf(sg2, sqrtf(p2) - 1.f, 1.f);
            const float n3 = fmaf(sg3, sqrtf(p3) - 1.f, 1.f);
            const float i0 = 1.f / (n0 + 1e-6f);
            const float i1 = 1.f / (n1 + 1e-6f);
            const float i2 = 1.f / (n2 + 1e-6f);
            const float i3 = 1.f / (n3 + 1e-6f);
            xr[e][0] *= i0; xr[e][1] *= i1; xr[e][2] *= i1; xr[e][3] *= i1;
            xr[e][4] *= i2; xr[e][5] *= i2; xr[e][6] *= i2; xr[e][7] *= i3;
            xl[e][0] += blc;
        }

        // ---- geometric product: xl_j += (sign*gpw)[i,k] * h_i * xr_k ----
        #pragma unroll
        for (int i = 0; i < 8; i++) {
            #pragma unroll
            for (int k = 0; k < 8; k++) {
                const int j = Jt[i][k];
                const float w = fgp[(i * 8 + k) * 32 + c];
                #pragma unroll
                for (int e = 0; e < EPW; e++)
                    xl[e][j] = fmaf(w, h[e][i] * xr[e][k], xl[e][j]);
            }
        }

        // ---- 1/sqrt(2) scale + MVLayerNorm + store ----
        const float is2 = 0.70710678118654752f;
        #pragma unroll
        for (int e = 0; e < EPW; e++) {
            float s = 0.f;
            #pragma unroll
            for (int i = 0; i < 8; i++) { xl[e][i] *= is2; s = fmaf(xl[e][i], xl[e][i], s); }
            float nc = sqrtf(s);
            #pragma unroll
            for (int off = 16; off; off >>= 1)
                nc += __shfl_xor_sync(0xffffffffu, nc, off);
            const float sc = alnc / (nc * (1.f / 32.f) + 1e-6f);

            float4* op = (float4*)(out + (b0 + e) * 256);
            op[c * 2]     = make_float4(xl[e][0]*sc, xl[e][1]*sc, xl[e][2]*sc, xl[e][3]*sc);
            op[c * 2 + 1] = make_float4(xl[e][4]*sc, xl[e][5]*sc, xl[e][6]*sc, xl[e][7]*sc);
        }
    }
}

extern "C" void kernel_launch(void* const* d_in, const int* in_sizes, int n_in,
                              void* d_out, int out_size) {
    const float* x      = (const float*)d_in[0];
    const float* w1     = (const float*)d_in[1];
    const float* b1     = (const float*)d_in[2];
    const float* a_relu = (const float*)d_in[3];
    const float* b_relu = (const float*)d_in[4];
    const float* wl     = (const float*)d_in[5];
    const float* bl     = (const float*)d_in[6];
    const float* wr     = (const float*)d_in[7];
    const float* a_norm = (const float*)d_in[8];
    const float* gp_w   = (const float*)d_in[9];
    const float* a_ln   = (const float*)d_in[10];
    const float* cayley = (const float*)d_in[11];
    float* out = (float*)d_out;

    const int B = in_sizes[0] / 128;     // [B, 16, 8]
    const int ngroups = B / EPW;         // B = 131072 divisible by 4
    const int blocks = 296;
    const int nwarps = blocks * WPB;
    const size_t shmem = 24576 * sizeof(float);  // 96 KB dynamic

    cudaFuncSetAttribute(cge_kernel, cudaFuncAttributeMaxDynamicSharedMemorySize,
                         (int)shmem);
    cge_kernel<<<blocks, NTHREADS, shmem>>>(x, w1, b1, a_relu, b_relu, wl, bl, wr,
                                            a_norm, gp_w, a_ln, cayley, out,
                                            ngroups, nwarps);
}